// round 15
// baseline (speedup 1.0000x reference)
#include <cuda_runtime.h>
#include <math.h>
#include <stdint.h>

#define MAXS 2048
#define HSIZE 8192
#define HMASK 8191
#define NBLK 148
#define NTHR 256
#define SMEMB 172544
#define TILE_MIN 1024
#define TMAX 1024

#define EPI_NONE 0
#define EPI_TANH 1
#define EPI_CADJ 2

typedef unsigned long long ull;

struct Params {
  const int *heads, *tails;
  const float *times;
  const float *node_rep, *cell_head, *hidden_head, *cell_tail, *hidden_tail;
  const float *Weh1, *Weh2, *beh, *Wet1, *Wet2, *bet;
  const float *Wxh, *Whh, *bh, *Wdh, *bdh;
  const float *Wxt, *Wht, *bt, *Wdt, *bdt;
  const float *Wc1, *Wc2;
  float *out;
  int S;
};

__device__ int g_cidH[MAXS], g_cidT[MAXS];
__device__ int g_slotNode[HSIZE];
__device__ int g_stepList[MAXS];
__device__ int g_waveOff[MAXS + 2];
__device__ int g_numWaves;

__device__ float c_rep[HSIZE * 128];
__device__ float c_ch [HSIZE * 128];
__device__ float c_hh [HSIZE * 128];
__device__ float c_ct [HSIZE * 128];
__device__ float c_ht [HSIZE * 128];
__device__ float c_rt [HSIZE];

// ---- tail-wave buffers + per-group flags ----
__device__ float bE1[TMAX*128], bE2[TMAX*128], bCJH[TMAX*128], bCJT[TMAX*128];
__device__ float bTh[TMAX*128], bHt[TMAX*128], bHnH[TMAX*128], bHnT[TMAX*128];
__device__ float bZ[TMAX*1024];
__device__ int g_flagA[MAXS], g_flagB[2*MAXS], g_flagC[2*MAXS];

__device__ unsigned g_barCnt;
__device__ volatile unsigned g_barGen;

__device__ __forceinline__ void grid_barrier() {
  __syncthreads();
  if (threadIdx.x == 0) {
    unsigned gen = g_barGen;
    __threadfence();
    if (atomicAdd(&g_barCnt, 1u) == gridDim.x - 1) {
      g_barCnt = 0; __threadfence(); g_barGen = gen + 1;
    } else {
      while (g_barGen == gen) { __nanosleep(32); }
    }
    __threadfence();
  }
  __syncthreads();
}

__device__ __forceinline__ float sigf(float x) { return 1.0f / (1.0f + expf(-x)); }
__device__ __forceinline__ void FFMA2(ull &d, ull a, ull b) {
  asm("fma.rn.f32x2 %0, %1, %2, %0;" : "+l"(d) : "l"(a), "l"(b));
}
__device__ __forceinline__ ull ADD2(ull a, ull b) {
  ull d; asm("add.rn.f32x2 %0, %1, %2;" : "=l"(d) : "l"(a), "l"(b)); return d;
}
__device__ __forceinline__ ull pack2(float a) {
  ull d; asm("mov.b64 %0, {%1, %1};" : "=l"(d) : "f"(a)); return d;
}
__device__ __forceinline__ void minit(uint32_t mb) {
  asm volatile("mbarrier.init.shared.b64 [%0], 1;" :: "r"(mb) : "memory");
}
__device__ __forceinline__ void etx(uint32_t mb, uint32_t bytes) {
  asm volatile("mbarrier.arrive.expect_tx.shared.b64 _, [%0], %1;" :: "r"(mb), "r"(bytes) : "memory");
}
__device__ __forceinline__ void bulkcp(uint32_t dst, const void* src, uint32_t bytes, uint32_t mb) {
  asm volatile("cp.async.bulk.shared::cta.global.mbarrier::complete_tx::bytes [%0], [%1], %2, [%3];"
               :: "r"(dst), "l"(src), "r"(bytes), "r"(mb) : "memory");
}
__device__ __forceinline__ void mwait(uint32_t mb, int ph) {
  asm volatile(
    "{\n\t.reg .pred P;\n\t"
    "W_%=: mbarrier.try_wait.parity.acquire.cta.shared::cta.b64 P, [%0], %1, 0x989680;\n\t"
    "@P bra D_%=;\n\t bra W_%=;\n\t D_%=:\n\t}"
    :: "r"(mb), "r"(ph) : "memory");
}

// Depth-4 pipeline of 16KB chunks.
struct Pipe { uint32_t ws, mb; int ic, wc; float* wsp; };
__device__ __forceinline__ void pissue(Pipe& P, const float* src) {
  int b = P.ic & 3;
  if (threadIdx.x == 0) {
    etx(P.mb + 8 * b, 16384);
    bulkcp(P.ws + b * 16384, src, 16384, P.mb + 8 * b);
  }
  P.ic++;
}
__device__ __forceinline__ const float* pwait(Pipe& P) {
  int b = P.wc & 3;
  mwait(P.mb + 8 * b, (P.wc >> 2) & 1);
  P.wc++;
  return P.wsp + b * 4096;
}

// ============================ scheduler =====================================
__global__ void __launch_bounds__(1024) scheduler_kernel(const int* heads, const int* tails, int S) {
  __shared__ int buf[HSIZE];
  __shared__ unsigned short sCH[MAXS], sCT[MAXS];
  __shared__ unsigned char asg[MAXS];
  __shared__ int sCnt, sBase, sW, sRemain;
  const int tid = threadIdx.x;
  for (int i = tid; i < HSIZE; i += 1024) { buf[i] = 0; g_slotNode[i] = -1; }
  for (int s = tid; s < S; s += 1024) { asg[s] = 0; g_flagA[s] = 0; }
  for (int s = tid; s < 2 * S; s += 1024) { g_flagB[s] = 0; g_flagC[s] = 0; }
  if (tid == 0) { sBase = 0; sW = 0; sRemain = S; }
  __syncthreads();
  for (int i = tid; i < 2 * S; i += 1024) {
    int step = i >> 1, isT = i & 1;
    int node = isT ? tails[step] : heads[step];
    int key = node + 1;
    unsigned slot = ((unsigned)node * 2654435761u) & HMASK;
    while (true) {
      int cur = buf[slot];
      if (cur == key) break;
      if (cur == 0) {
        int old = atomicCAS(&buf[slot], 0, key);
        if (old == 0) { g_slotNode[slot] = node; break; }
        if (old == key) break;
      }
      slot = (slot + 1u) & HMASK;
    }
    if (isT) { sCT[step] = (unsigned short)slot; g_cidT[step] = (int)slot; }
    else     { sCH[step] = (unsigned short)slot; g_cidH[step] = (int)slot; }
  }
  __syncthreads();
  while (sRemain > 0) {
    for (int s = tid; s < S; s += 1024)
      if (!asg[s]) { buf[sCH[s]] = 0x7FFFFFFF; buf[sCT[s]] = 0x7FFFFFFF; }
    __syncthreads();
    for (int s = tid; s < S; s += 1024)
      if (!asg[s]) { atomicMin(&buf[sCH[s]], 2 * s); atomicMin(&buf[sCT[s]], 2 * s + 1); }
    if (tid == 0) sCnt = 0;
    __syncthreads();
    for (int s = tid; s < S; s += 1024)
      if (!asg[s]) {
        int ch = sCH[s], ct = sCT[s];
        if (buf[ch] == 2 * s && (ct == ch || buf[ct] == 2 * s + 1)) {
          asg[s] = 1;
          g_stepList[sBase + atomicAdd(&sCnt, 1)] = s;
        }
      }
    __syncthreads();
    if (tid == 0) {
      g_waveOff[sW] = sBase; sBase += sCnt; sRemain -= sCnt; sW += 1; g_waveOff[sW] = sBase;
    }
    __syncthreads();
  }
  if (tid == 0) g_numWaves = sW;
}

// ====== N=128 GEMM: warp = 8 rows x 64 cols x k-split 2, depth-4 pipe ======
__device__ void gemm128(Pipe& P, const float* A1, const float* A2,
                        const float* W1, const float* W2, const float* bias,
                        int epi, const float* CAp, const float* dec,
                        float* outS, float* const* outG, float* red) {
  const int tid = threadIdx.x, w = tid >> 5, l = tid & 31;
  const int ks = (w >> 2) << 4;
  const int rg = ((w >> 1) & 1) << 3;
  const int cbase = (w & 1) * 64 + l * 2;
  const int nch = A2 ? 8 : 4;
  ull acc[8];
#pragma unroll
  for (int r = 0; r < 8; ++r) acc[r] = 0;
  int npf = nch < 3 ? nch : 3;
  for (int c = 0; c < npf; ++c)
    pissue(P, (c < 4 ? W1 : W2) + (c & 3) * 32 * 128);
  for (int c = 0; c < nch; ++c) {
    if (c + 3 < nch) {
      int n = c + 3;
      pissue(P, (n < 4 ? W1 : W2) + (n & 3) * 32 * 128);
    }
    const float* Wc = pwait(P);
    const float* A = (c < 4) ? A1 : A2;
    const int k0 = (c & 3) * 32 + ks;
#pragma unroll
    for (int kg = 0; kg < 4; ++kg) {
      float4 av[8];
#pragma unroll
      for (int r = 0; r < 8; ++r)
        av[r] = *(const float4*)&A[(rg + r) * 128 + k0 + kg * 4];
#pragma unroll
      for (int kk = 0; kk < 4; ++kk) {
        ull wv = *(const ull*)&Wc[(ks + kg * 4 + kk) * 128 + cbase];
#pragma unroll
        for (int r = 0; r < 8; ++r)
          FFMA2(acc[r], pack2(((const float*)&av[r])[kk]), wv);
      }
    }
    __syncthreads();
  }
  // k-split merge: warps 4-7 publish; partner = w - 4
  ull* rd = (ull*)red;
  if (w >= 4) {
    ull* dst = rd + (((w - 4) * 32 + l) << 3);
#pragma unroll
    for (int r = 0; r < 8; ++r) dst[r] = acc[r];
  }
  __syncthreads();
  if (w < 4) {
    const ull* src = rd + ((w * 32 + l) << 3);
    union U { ull u; float2 f; };
#pragma unroll
    for (int r = 0; r < 8; ++r) {
      acc[r] = ADD2(acc[r], src[r]);
      int row = rg + r;
      U u; u.u = acc[r];
      float vals[2] = {u.f.x, u.f.y};
      float* og = outG ? outG[row] : 0;
#pragma unroll
      for (int j = 0; j < 2; ++j) {
        int col = cbase + j;
        float v = vals[j];
        if (bias) v += bias[col];
        if (epi == EPI_TANH) v = tanhf(v);
        else if (epi == EPI_CADJ) {
          float cs = tanhf(v);
          v = CAp[row * 128 + col] + cs * (dec[row] - 1.0f);
        }
        if (outS) outS[row * 128 + col] = v;
        else if (og) og[col] = v;
      }
    }
  }
  __syncthreads();
}

// ====== N=512 gates GEMM: warp = 8 rows x 128 cols, 32x16KB chunks =========
__device__ void gemm512(Pipe& P, const float* A1, const float* A2,
                        const float* Wx, const float* Wh, const float* bias, float* Z) {
  const int tid = threadIdx.x, w = tid >> 5, l = tid & 31;
  const int rg = (w >> 2) << 3;
  const int cg = (w & 3) << 7;
  ull acc[8][2];
#pragma unroll
  for (int r = 0; r < 8; ++r) { acc[r][0] = 0; acc[r][1] = 0; }
  for (int c = 0; c < 3; ++c) pissue(P, Wx + c * 8 * 512);
  for (int c = 0; c < 32; ++c) {
    if (c + 3 < 32) {
      int n = c + 3;
      pissue(P, (n < 16 ? Wx : Wh) + (n & 15) * 8 * 512);
    }
    const float* Wc = pwait(P);
    const float* A = (c < 16) ? A1 : A2;
    const int k0 = (c & 15) * 8;
#pragma unroll
    for (int kg = 0; kg < 2; ++kg) {
      float4 av[8];
#pragma unroll
      for (int r = 0; r < 8; ++r)
        av[r] = *(const float4*)&A[(rg + r) * 128 + k0 + kg * 4];
#pragma unroll
      for (int kk = 0; kk < 4; ++kk) {
        ulonglong2 wv = *(const ulonglong2*)&Wc[(kg * 4 + kk) * 512 + cg + (l << 2)];
#pragma unroll
        for (int r = 0; r < 8; ++r) {
          ull a = pack2(((const float*)&av[r])[kk]);
          FFMA2(acc[r][0], a, wv.x);
          FFMA2(acc[r][1], a, wv.y);
        }
      }
    }
    __syncthreads();
  }
  union U { ull u; float2 f; };
#pragma unroll
  for (int r = 0; r < 8; ++r) {
    U u0, u1; u0.u = acc[r][0]; u1.u = acc[r][1];
    float vals[4] = {u0.f.x, u0.f.y, u1.f.x, u1.f.y};
#pragma unroll
    for (int j = 0; j < 4; ++j) {
      int col = cg + (l << 2) + j;
      Z[(rg + r) * 512 + col] = vals[j] + bias[col];
    }
  }
  __syncthreads();
}

// ============================== main kernel =================================
__global__ void __launch_bounds__(NTHR) main_kernel(Params p) {
  extern __shared__ float sm[];
  float *X1 = sm, *X2 = sm + 2048, *E1 = sm + 4096, *E2 = sm + 6144;
  float *H1 = sm + 8192, *H2 = sm + 10240, *S1 = sm + 12288, *S2 = sm + 14336;
  float *CAb = sm + 16384, *Z = sm + 18432, *WS = sm + 26624;
  float *misc = sm + 43008;
  uint64_t* mbar = (uint64_t*)misc;                 // 4 mbarriers = 32B
  int *slotH = (int*)(misc + 8), *slotT = slotH + 16, *valid = slotT + 16;
  float *decH = (float*)(valid + 16), *decT = decH + 16;
  float **og = (float**)(decT + 16);

  const int tid = threadIdx.x;
  const int gsize = gridDim.x * blockDim.x;
  const int gtid = blockIdx.x * blockDim.x + tid;
  const int S = p.S;

  Pipe P;
  P.wsp = WS;
  P.ws = (uint32_t)__cvta_generic_to_shared(WS);
  P.mb = (uint32_t)__cvta_generic_to_shared(mbar);
  P.ic = 0; P.wc = 0;
  if (tid == 0) { minit(P.mb); minit(P.mb + 8); minit(P.mb + 16); minit(P.mb + 24); }
  __syncthreads();

  for (int e = gtid; e < HSIZE * 32; e += gsize) {
    int slot = e >> 5, q = (e & 31) << 2;
    int node = g_slotNode[slot];
    if (node < 0) continue;
    size_t src = (size_t)node * 128 + q;
    size_t dst = (size_t)slot * 128 + q;
    *(float4*)&c_rep[dst] = *(const float4*)&p.node_rep[src];
    *(float4*)&c_ch[dst]  = *(const float4*)&p.cell_head[src];
    *(float4*)&c_hh[dst]  = *(const float4*)&p.hidden_head[src];
    *(float4*)&c_ct[dst]  = *(const float4*)&p.cell_tail[src];
    *(float4*)&c_ht[dst]  = *(const float4*)&p.hidden_tail[src];
    if (q == 0) c_rt[slot] = 0.0f;
  }
  grid_barrier();

  const int nW = g_numWaves;
  for (int w = 0; w < nW; ++w) {
    const int s0 = g_waveOff[w];
    const int M = g_waveOff[w + 1] - s0;

    if (M >= TILE_MIN) {
      const int mT = (M + 15) >> 4;
      for (int job = blockIdx.x; job < mT; job += gridDim.x) {
        int m0 = job * 16;
        if (tid < 16) {
          int m = m0 + tid;
          int v = (m < M);
          int step = g_stepList[s0 + (v ? m : (M - 1))];
          int ch = g_cidH[step], ct = g_cidT[step];
          slotH[tid] = ch; slotT[tid] = ct; valid[tid] = v;
          float tm = p.times[step];
          decH[tid] = expf(-(tm - c_rt[ch]));
          decT[tid] = expf(-(tm - c_rt[ct]));
          if (v) { c_rt[ch] = tm; c_rt[ct] = tm; }
        }
        __syncthreads();
        for (int e = tid; e < 512; e += NTHR) {
          int r = e >> 5, q = (e & 31) << 2;
          int ch = slotH[r], ct = slotT[r];
          float4 rh = *(const float4*)&c_rep[ch * 128 + q];
          float4 rt = *(const float4*)&c_rep[ct * 128 + q];
          *(float4*)&X1[r * 128 + q] = rh;
          *(float4*)&X2[r * 128 + q] = rt;
          *(float4*)&H1[r * 128 + q] = *(const float4*)&c_hh[ch * 128 + q];
          *(float4*)&H2[r * 128 + q] = *(const float4*)&c_ht[ct * 128 + q];
          *(float4*)&S1[r * 128 + q] = *(const float4*)&c_ht[ch * 128 + q];
          *(float4*)&S2[r * 128 + q] = *(const float4*)&c_hh[ct * 128 + q];
          if (valid[r]) {
            int step = g_stepList[s0 + m0 + r];
            *(float4*)&p.out[(size_t)step * 128 + q] = rh;
            *(float4*)&p.out[(size_t)(S + step) * 128 + q] = rt;
          }
        }
        __syncthreads();

        // edges as dual gemm128s
        gemm128(P, X1, X2, p.Weh1, p.Weh2, p.beh, EPI_TANH, 0, 0, E1, 0, Z);
        gemm128(P, X1, X2, p.Wet1, p.Wet2, p.bet, EPI_TANH, 0, 0, E2, 0, Z);

        for (int e = tid; e < 512; e += NTHR) {
          int r = e >> 5, q = (e & 31) << 2;
          *(float4*)&CAb[r * 128 + q] = *(const float4*)&c_ch[slotH[r] * 128 + q];
        }
        __syncthreads();
        gemm128(P, CAb, 0, p.Wdh, 0, p.bdh, EPI_CADJ, CAb, decH, X1, 0, Z);
        for (int e = tid; e < 512; e += NTHR) {
          int r = e >> 5, q = (e & 31) << 2;
          *(float4*)&CAb[r * 128 + q] = *(const float4*)&c_ct[slotT[r] * 128 + q];
        }
        __syncthreads();
        gemm128(P, CAb, 0, p.Wdt, 0, p.bdt, EPI_CADJ, CAb, decT, X2, 0, Z);

        for (int side = 0; side < 2; ++side) {
          if (side == 0) gemm512(P, E1, H1, p.Wxh, p.Whh, p.bh, Z);
          else           gemm512(P, E2, H2, p.Wxt, p.Wht, p.bt, Z);
          float* Xc = side ? X2 : X1;
          float* cel = side ? c_ct : c_ch;
          float* hid = side ? c_ht : c_hh;
          int* slot = side ? slotT : slotH;
          for (int e = tid; e < 2048; e += NTHR) {
            int r = e >> 7, c = e & 127;
            if (!valid[r]) continue;
            const float* z = &Z[r * 512];
            float ii = sigf(z[c]), ff = sigf(z[128 + c]);
            float oo = sigf(z[256 + c]), gg = tanhf(z[384 + c]);
            float cn = ff * Xc[r * 128 + c] + ii * gg;
            float hn = oo * tanhf(cn);
            Xc[r * 128 + c] = hn;
            cel[slot[r] * 128 + c] = cn;
            hid[slot[r] * 128 + c] = hn;
          }
          __syncthreads();
        }

        if (tid < 16)
          og[tid] = (valid[tid] && slotH[tid] != slotT[tid]) ? (c_rep + slotH[tid] * 128) : 0;
        __syncthreads();
        gemm128(P, X1, S1, p.Wc1, p.Wc2, 0, EPI_TANH, 0, 0, 0, og, Z);
        if (tid < 16) og[tid] = valid[tid] ? (c_rep + slotT[tid] * 128) : 0;
        __syncthreads();
        gemm128(P, S2, X2, p.Wc1, p.Wc2, 0, EPI_TANH, 0, 0, 0, og, Z);
      }
    } else {
      // ===== group-batched flag-gated tail: 8 steps per job, W read once ===
      float *vA = sm, *vB = sm + 1024, *red = sm + 2048, *sdec = sm + 3072;
      const int nG = (M + 7) >> 3;
      const int nJ = 16 * nG;
      for (int j = blockIdx.x; j < nJ; j += NBLK) {
        int stage, g, sub;
        if (j < 4 * nG)       { stage = 0; g = j >> 2; sub = j & 3; }
        else if (j < 12 * nG) { stage = 1; int q = j - 4 * nG; g = q >> 3; sub = q & 7; }
        else if (j < 14 * nG) { stage = 2; int q = j - 12 * nG; g = q >> 1; sub = q & 1; }
        else                  { stage = 3; int q = j - 14 * nG; g = q >> 1; sub = q & 1; }
        const int pos = s0 + g * 8;
        const int cnt = min(8, M - g * 8);
        const int t = tid, col = t & 127, half = t >> 7;

        if (stage == 0) {
          if (sub < 2) {
            for (int e = t; e < cnt * 128; e += NTHR) {
              int r = e >> 7, c = e & 127;
              int step = g_stepList[pos + r];
              float rh = c_rep[g_cidH[step] * 128 + c];
              float rt = c_rep[g_cidT[step] * 128 + c];
              vA[r * 128 + c] = rh; vB[r * 128 + c] = rt;
              if (sub == 0) {
                p.out[(size_t)step * 128 + c] = rh;
                p.out[(size_t)(S + step) * 128 + c] = rt;
              }
            }
            __syncthreads();
            const float* W = half ? (sub ? p.Wet2 : p.Weh2) : (sub ? p.Wet1 : p.Weh1);
            const float* A = half ? vB : vA;
            float acc[8];
#pragma unroll
            for (int r = 0; r < 8; ++r) acc[r] = 0;
            for (int k0 = 0; k0 < 128; k0 += 4) {
              float4 av[8];
#pragma unroll
              for (int r = 0; r < 8; ++r) av[r] = *(const float4*)&A[r * 128 + k0];
#pragma unroll
              for (int kk = 0; kk < 4; ++kk) {
                float wv = W[(k0 + kk) * 128 + col];
#pragma unroll
                for (int r = 0; r < 8; ++r) acc[r] += ((const float*)&av[r])[kk] * wv;
              }
            }
            if (half)
#pragma unroll
              for (int r = 0; r < 8; ++r) red[r * 128 + col] = acc[r];
            __syncthreads();
            if (!half) {
              const float* bb = sub ? p.bet : p.beh;
              float* E = sub ? bE2 : bE1;
              for (int r = 0; r < cnt; ++r)
                E[(g * 8 + r) * 128 + col] = tanhf(acc[r] + red[r * 128 + col] + bb[col]);
            }
          } else {
            int isH = (sub == 2);
            for (int e = t; e < cnt * 128; e += NTHR) {
              int r = e >> 7, c = e & 127;
              int step = g_stepList[pos + r];
              int slot = isH ? g_cidH[step] : g_cidT[step];
              vA[r * 128 + c] = (isH ? c_ch : c_ct)[slot * 128 + c];
              if (isH) bTh[(g * 8 + r) * 128 + c] = c_ht[g_cidH[step] * 128 + c];
              else     bHt[(g * 8 + r) * 128 + c] = c_hh[g_cidT[step] * 128 + c];
              if (c == 0) sdec[r] = expf(-(p.times[step] - c_rt[slot]));
            }
            __syncthreads();
            const float* W = isH ? p.Wdh : p.Wdt;
            float acc[8];
#pragma unroll
            for (int r = 0; r < 8; ++r) acc[r] = 0;
            for (int k0 = half * 64; k0 < half * 64 + 64; k0 += 4) {
              float4 av[8];
#pragma unroll
              for (int r = 0; r < 8; ++r) av[r] = *(const float4*)&vA[r * 128 + k0];
#pragma unroll
              for (int kk = 0; kk < 4; ++kk) {
                float wv = W[(k0 + kk) * 128 + col];
#pragma unroll
                for (int r = 0; r < 8; ++r) acc[r] += ((const float*)&av[r])[kk] * wv;
              }
            }
            if (half)
#pragma unroll
              for (int r = 0; r < 8; ++r) red[r * 128 + col] = acc[r];
            __syncthreads();
            if (!half) {
              const float* bd = isH ? p.bdh : p.bdt;
              float* CJ = isH ? bCJH : bCJT;
              for (int r = 0; r < cnt; ++r) {
                float cs = tanhf(acc[r] + red[r * 128 + col] + bd[col]);
                CJ[(g * 8 + r) * 128 + col] = vA[r * 128 + col] + cs * (sdec[r] - 1.0f);
              }
            }
          }
          __threadfence();
          __syncthreads();
          if (t == 0) atomicAdd(&g_flagA[pos], 1);
        } else if (stage == 1) {
          int side = sub & 1, gate = sub >> 1;
          if (t == 0) {
            while (atomicAdd(&g_flagA[pos], 0) < 4) __nanosleep(64);
            __threadfence();
          }
          __syncthreads();
          for (int e = t; e < cnt * 128; e += NTHR) {
            int r = e >> 7, c = e & 127;
            int step = g_stepList[pos + r];
            vA[r * 128 + c] = (side ? bE2 : bE1)[(g * 8 + r) * 128 + c];
            vB[r * 128 + c] = side ? c_ht[g_cidT[step] * 128 + c]
                                   : c_hh[g_cidH[step] * 128 + c];
          }
          __syncthreads();
          const float* W = half ? (side ? p.Wht : p.Whh) : (side ? p.Wxt : p.Wxh);
          const float* A = half ? vB : vA;
          int gcol = gate * 128 + col;
          float acc[8];
#pragma unroll
          for (int r = 0; r < 8; ++r) acc[r] = 0;
          for (int k0 = 0; k0 < 128; k0 += 4) {
            float4 av[8];
#pragma unroll
            for (int r = 0; r < 8; ++r) av[r] = *(const float4*)&A[r * 128 + k0];
#pragma unroll
            for (int kk = 0; kk < 4; ++kk) {
              float wv = W[(k0 + kk) * 512 + gcol];
#pragma unroll
              for (int r = 0; r < 8; ++r) acc[r] += ((const float*)&av[r])[kk] * wv;
            }
          }
          if (half)
#pragma unroll
            for (int r = 0; r < 8; ++r) red[r * 128 + col] = acc[r];
          __syncthreads();
          if (!half) {
            const float* bb = side ? p.bt : p.bh;
            for (int r = 0; r < cnt; ++r)
              bZ[(g * 8 + r) * 1024 + side * 512 + gcol] =
                  acc[r] + red[r * 128 + col] + bb[gcol];
          }
          __threadfence();
          __syncthreads();
          if (t == 0) atomicAdd(&g_flagB[2 * pos + side], 1);
        } else if (stage == 2) {
          int side = sub;
          if (t == 0) {
            while (atomicAdd(&g_flagB[2 * pos + side], 0) < 4) __nanosleep(64);
            __threadfence();
          }
          __syncthreads();
          for (int e = t; e < cnt * 128; e += NTHR) {
            int r = e >> 7, c = e & 127;
            int step = g_stepList[pos + r];
            int slot = side ? g_cidT[step] : g_cidH[step];
            const float* z = &bZ[(g * 8 + r) * 1024 + side * 512];
            float ii = sigf(z[c]), ff = sigf(z[128 + c]);
            float oo = sigf(z[256 + c]), gg = tanhf(z[384 + c]);
            float cj = (side ? bCJT : bCJH)[(g * 8 + r) * 128 + c];
            float cn = ff * cj + ii * gg;
            float hn = oo * tanhf(cn);
            (side ? bHnT : bHnH)[(g * 8 + r) * 128 + c] = hn;
            (side ? c_ct : c_ch)[slot * 128 + c] = cn;
            (side ? c_ht : c_hh)[slot * 128 + c] = hn;
            if (c == 0) c_rt[slot] = p.times[step];
          }
          __threadfence();
          __syncthreads();
          if (t == 0) atomicAdd(&g_flagC[2 * pos + side], 1);
        } else {
          int side = sub;
          if (t == 0) {
            while (atomicAdd(&g_flagC[2 * pos + side], 0) < 1) __nanosleep(64);
            __threadfence();
          }
          __syncthreads();
          for (int e = t; e < cnt * 128; e += NTHR) {
            int r = e >> 7, c = e & 127;
            vA[r * 128 + c] = (side ? bHt : bHnH)[(g * 8 + r) * 128 + c];
            vB[r * 128 + c] = (side ? bHnT : bTh)[(g * 8 + r) * 128 + c];
          }
          __syncthreads();
          const float* W = half ? p.Wc2 : p.Wc1;
          const float* A = half ? vB : vA;
          float acc[8];
#pragma unroll
          for (int r = 0; r < 8; ++r) acc[r] = 0;
          for (int k0 = 0; k0 < 128; k0 += 4) {
            float4 av[8];
#pragma unroll
            for (int r = 0; r < 8; ++r) av[r] = *(const float4*)&A[r * 128 + k0];
#pragma unroll
            for (int kk = 0; kk < 4; ++kk) {
              float wv = W[(k0 + kk) * 128 + col];
#pragma unroll
              for (int r = 0; r < 8; ++r) acc[r] += ((const float*)&av[r])[kk] * wv;
            }
          }
          if (half)
#pragma unroll
            for (int r = 0; r < 8; ++r) red[r * 128 + col] = acc[r];
          __syncthreads();
          if (!half) {
            for (int r = 0; r < cnt; ++r) {
              int step = g_stepList[pos + r];
              int ch = g_cidH[step], ct = g_cidT[step];
              if (side || ch != ct)
                c_rep[(side ? ct : ch) * 128 + col] =
                    tanhf(acc[r] + red[r * 128 + col]);
            }
          }
          __syncthreads();
        }
      }
    }
    grid_barrier();
  }
}

// ============================================================================
extern "C" void kernel_launch(void* const* d_in, const int* in_sizes, int n_in,
                              void* d_out, int out_size) {
  Params p;
  p.heads = (const int*)d_in[0];  p.tails = (const int*)d_in[1];
  p.times = (const float*)d_in[2];
  p.node_rep = (const float*)d_in[3];  p.cell_head = (const float*)d_in[4];
  p.hidden_head = (const float*)d_in[5]; p.cell_tail = (const float*)d_in[6];
  p.hidden_tail = (const float*)d_in[7];
  p.Weh1 = (const float*)d_in[8];  p.Weh2 = (const float*)d_in[9];  p.beh = (const float*)d_in[10];
  p.Wet1 = (const float*)d_in[11]; p.Wet2 = (const float*)d_in[12]; p.bet = (const float*)d_in[13];
  p.Wxh = (const float*)d_in[14];  p.Whh = (const float*)d_in[15];  p.bh = (const float*)d_in[16];
  p.Wdh = (const float*)d_in[17];  p.bdh = (const float*)d_in[18];
  p.Wxt = (const float*)d_in[19];  p.Wht = (const float*)d_in[20];  p.bt = (const float*)d_in[21];
  p.Wdt = (const float*)d_in[22];  p.bdt = (const float*)d_in[23];
  p.Wc1 = (const float*)d_in[24];  p.Wc2 = (const float*)d_in[25];
  p.out = (float*)d_out;
  p.S = in_sizes[0];

  cudaFuncSetAttribute(main_kernel, cudaFuncAttributeMaxDynamicSharedMemorySize, SMEMB);
  scheduler_kernel<<<1, 1024>>>(p.heads, p.tails, p.S);
  main_kernel<<<NBLK, NTHR, SMEMB>>>(p);
}

// round 16
// speedup vs baseline: 1.1162x; 1.1162x over previous
#include <cuda_runtime.h>
#include <math.h>
#include <stdint.h>

#define MAXS 2048
#define HSIZE 8192
#define HMASK 8191
#define NBLK 148
#define NTHR 512
#define SMEMB 172544
#define TILE_MIN 1024
#define TMAX 1024

#define EPI_NONE 0
#define EPI_TANH 1
#define EPI_CADJ 2

typedef unsigned long long ull;

struct Params {
  const int *heads, *tails;
  const float *times;
  const float *node_rep, *cell_head, *hidden_head, *cell_tail, *hidden_tail;
  const float *Weh1, *Weh2, *beh, *Wet1, *Wet2, *bet;
  const float *Wxh, *Whh, *bh, *Wdh, *bdh;
  const float *Wxt, *Wht, *bt, *Wdt, *bdt;
  const float *Wc1, *Wc2;
  float *out;
  int S;
};

__device__ int g_cidH[MAXS], g_cidT[MAXS];
__device__ int g_slotNode[HSIZE];
__device__ int g_stepList[MAXS];
__device__ int g_waveOff[MAXS + 2];
__device__ int g_numWaves;

__device__ float c_rep[HSIZE * 128];
__device__ float c_ch [HSIZE * 128];
__device__ float c_hh [HSIZE * 128];
__device__ float c_ct [HSIZE * 128];
__device__ float c_ht [HSIZE * 128];
__device__ float c_rt [HSIZE];

// ---- tail-wave buffers + per-group flags ----
__device__ float bE1[TMAX*128], bE2[TMAX*128], bCJH[TMAX*128], bCJT[TMAX*128];
__device__ float bTh[TMAX*128], bHt[TMAX*128], bHnH[TMAX*128], bHnT[TMAX*128];
__device__ float bZ[TMAX*1024];
__device__ int g_flagA[MAXS], g_flagB[2*MAXS], g_flagC[2*MAXS];

__device__ unsigned g_barCnt;
__device__ volatile unsigned g_barGen;

__device__ __forceinline__ void grid_barrier() {
  __syncthreads();
  if (threadIdx.x == 0) {
    unsigned gen = g_barGen;
    __threadfence();
    if (atomicAdd(&g_barCnt, 1u) == gridDim.x - 1) {
      g_barCnt = 0; __threadfence(); g_barGen = gen + 1;
    } else {
      while (g_barGen == gen) { __nanosleep(32); }
    }
    __threadfence();
  }
  __syncthreads();
}

__device__ __forceinline__ float sigf(float x) { return 1.0f / (1.0f + expf(-x)); }
__device__ __forceinline__ void FFMA2(ull &d, ull a, ull b) {
  asm("fma.rn.f32x2 %0, %1, %2, %0;" : "+l"(d) : "l"(a), "l"(b));
}
__device__ __forceinline__ ull ADD2(ull a, ull b) {
  ull d; asm("add.rn.f32x2 %0, %1, %2;" : "=l"(d) : "l"(a), "l"(b)); return d;
}
__device__ __forceinline__ ull pack2(float a) {
  ull d; asm("mov.b64 %0, {%1, %1};" : "=l"(d) : "f"(a)); return d;
}
__device__ __forceinline__ void minit(uint32_t mb) {
  asm volatile("mbarrier.init.shared.b64 [%0], 1;" :: "r"(mb) : "memory");
}
__device__ __forceinline__ void etx(uint32_t mb, uint32_t bytes) {
  asm volatile("mbarrier.arrive.expect_tx.shared.b64 _, [%0], %1;" :: "r"(mb), "r"(bytes) : "memory");
}
__device__ __forceinline__ void bulkcp(uint32_t dst, const void* src, uint32_t bytes, uint32_t mb) {
  asm volatile("cp.async.bulk.shared::cta.global.mbarrier::complete_tx::bytes [%0], [%1], %2, [%3];"
               :: "r"(dst), "l"(src), "r"(bytes), "r"(mb) : "memory");
}
__device__ __forceinline__ void mwait(uint32_t mb, int ph) {
  asm volatile(
    "{\n\t.reg .pred P;\n\t"
    "W_%=: mbarrier.try_wait.parity.acquire.cta.shared::cta.b64 P, [%0], %1, 0x989680;\n\t"
    "@P bra D_%=;\n\t bra W_%=;\n\t D_%=:\n\t}"
    :: "r"(mb), "r"(ph) : "memory");
}

struct Pipe { uint32_t ws, mb; int ic, wc; float* wsp; };
__device__ __forceinline__ void pissue(Pipe& P, const float* s1, uint32_t bytes, const float* s2) {
  int b = P.ic & 1;
  if (threadIdx.x == 0) {
    etx(P.mb + 8 * b, s2 ? 2 * bytes : bytes);
    bulkcp(P.ws + b * 32768, s1, bytes, P.mb + 8 * b);
    if (s2) bulkcp(P.ws + b * 32768 + bytes, s2, bytes, P.mb + 8 * b);
  }
  P.ic++;
}
__device__ __forceinline__ const float* pwait(Pipe& P) {
  int b = P.wc & 1;
  mwait(P.mb + 8 * b, (P.wc >> 1) & 1);
  P.wc++;
  return P.wsp + b * 8192;
}

// ============================ scheduler =====================================
__global__ void __launch_bounds__(1024) scheduler_kernel(const int* heads, const int* tails, int S) {
  __shared__ int buf[HSIZE];
  __shared__ unsigned short sCH[MAXS], sCT[MAXS];
  __shared__ unsigned char asg[MAXS];
  __shared__ int sCnt, sBase, sW, sRemain;
  const int tid = threadIdx.x;
  for (int i = tid; i < HSIZE; i += 1024) { buf[i] = 0; g_slotNode[i] = -1; }
  for (int s = tid; s < S; s += 1024) { asg[s] = 0; g_flagA[s] = 0; }
  for (int s = tid; s < 2 * S; s += 1024) { g_flagB[s] = 0; g_flagC[s] = 0; }
  if (tid == 0) { sBase = 0; sW = 0; sRemain = S; }
  __syncthreads();
  for (int i = tid; i < 2 * S; i += 1024) {
    int step = i >> 1, isT = i & 1;
    int node = isT ? tails[step] : heads[step];
    int key = node + 1;
    unsigned slot = ((unsigned)node * 2654435761u) & HMASK;
    while (true) {
      int cur = buf[slot];
      if (cur == key) break;
      if (cur == 0) {
        int old = atomicCAS(&buf[slot], 0, key);
        if (old == 0) { g_slotNode[slot] = node; break; }
        if (old == key) break;
      }
      slot = (slot + 1u) & HMASK;
    }
    if (isT) { sCT[step] = (unsigned short)slot; g_cidT[step] = (int)slot; }
    else     { sCH[step] = (unsigned short)slot; g_cidH[step] = (int)slot; }
  }
  __syncthreads();
  while (sRemain > 0) {
    for (int s = tid; s < S; s += 1024)
      if (!asg[s]) { buf[sCH[s]] = 0x7FFFFFFF; buf[sCT[s]] = 0x7FFFFFFF; }
    __syncthreads();
    for (int s = tid; s < S; s += 1024)
      if (!asg[s]) { atomicMin(&buf[sCH[s]], 2 * s); atomicMin(&buf[sCT[s]], 2 * s + 1); }
    if (tid == 0) sCnt = 0;
    __syncthreads();
    for (int s = tid; s < S; s += 1024)
      if (!asg[s]) {
        int ch = sCH[s], ct = sCT[s];
        if (buf[ch] == 2 * s && (ct == ch || buf[ct] == 2 * s + 1)) {
          asg[s] = 1;
          g_stepList[sBase + atomicAdd(&sCnt, 1)] = s;
        }
      }
    __syncthreads();
    if (tid == 0) {
      g_waveOff[sW] = sBase; sBase += sCnt; sRemain -= sCnt; sW += 1; g_waveOff[sW] = sBase;
    }
    __syncthreads();
  }
  if (tid == 0) g_numWaves = sW;
}

// ====== merged edge GEMM: N=256 (E1|E2), 16 warps = 4 rows x 64 cols =======
__device__ void gemmEdge(Pipe& P, const Params& p, const float* X1, const float* X2,
                         float* E1, float* E2) {
  const int tid = threadIdx.x, w = tid >> 5, l = tid & 31;
  const int rg = (w >> 2) << 2;            // 4 rows: 0,4,8,12
  const int cg = w & 3;
  const int mat = cg >> 1;                 // 0 = Weh, 1 = Wet
  const int cbase = (cg & 1) * 64 + l * 2;
  ull acc[4];
#pragma unroll
  for (int r = 0; r < 4; ++r) acc[r] = 0;
  pissue(P, p.Weh1, 16384, p.Wet1);
  for (int c = 0; c < 8; ++c) {
    if (c < 7) {
      const float* Wa = (c + 1 < 4) ? p.Weh1 : p.Weh2;
      const float* Wb = (c + 1 < 4) ? p.Wet1 : p.Wet2;
      int k0 = ((c + 1) & 3) * 32;
      pissue(P, Wa + k0 * 128, 16384, Wb + k0 * 128);
    }
    const float* Wc = pwait(P) + mat * 4096;
    const float* A = (c < 4) ? X1 : X2;
    const int k0 = (c & 3) * 32;
#pragma unroll
    for (int kg = 0; kg < 8; ++kg) {
      float4 av[4];
#pragma unroll
      for (int r = 0; r < 4; ++r)
        av[r] = *(const float4*)&A[(rg + r) * 128 + k0 + kg * 4];
#pragma unroll
      for (int kk = 0; kk < 4; ++kk) {
        ull wv = *(const ull*)&Wc[(kg * 4 + kk) * 128 + cbase];
#pragma unroll
        for (int r = 0; r < 4; ++r)
          FFMA2(acc[r], pack2(((const float*)&av[r])[kk]), wv);
      }
    }
    __syncthreads();
  }
  const float* bias = mat ? p.bet : p.beh;
  float* E = mat ? E2 : E1;
  union U { ull u; float2 f; };
#pragma unroll
  for (int r = 0; r < 4; ++r) {
    U u; u.u = acc[r];
    E[(rg + r) * 128 + cbase]     = tanhf(u.f.x + bias[cbase]);
    E[(rg + r) * 128 + cbase + 1] = tanhf(u.f.y + bias[cbase + 1]);
  }
  __syncthreads();
}

// ====== N=128 GEMM: 16 warps = 2ks x 4rg(4 rows) x 2cg(64 cols) ============
__device__ void gemm128(Pipe& P, const float* A1, const float* A2,
                        const float* W1, const float* W2, const float* bias,
                        int epi, const float* CAp, const float* dec,
                        float* outS, float* const* outG, float* red) {
  const int tid = threadIdx.x, w = tid >> 5, l = tid & 31;
  const int ks = (w >> 3) << 4;            // 0 or 16
  const int rg = ((w >> 1) & 3) << 2;      // 0,4,8,12
  const int cbase = (w & 1) * 64 + l * 2;
  const int nch = A2 ? 8 : 4;
  ull acc[4];
#pragma unroll
  for (int r = 0; r < 4; ++r) acc[r] = 0;
  pissue(P, W1, 16384, 0);
  for (int c = 0; c < nch; ++c) {
    if (c + 1 < nch) {
      const float* W = (c + 1 < 4) ? W1 : W2;
      pissue(P, W + ((c + 1) & 3) * 32 * 128, 16384, 0);
    }
    const float* Wc = pwait(P);
    const float* A = (c < 4) ? A1 : A2;
    const int k0 = (c & 3) * 32 + ks;
#pragma unroll
    for (int kg = 0; kg < 4; ++kg) {
      float4 av[4];
#pragma unroll
      for (int r = 0; r < 4; ++r)
        av[r] = *(const float4*)&A[(rg + r) * 128 + k0 + kg * 4];
#pragma unroll
      for (int kk = 0; kk < 4; ++kk) {
        ull wv = *(const ull*)&Wc[(ks + kg * 4 + kk) * 128 + cbase];
#pragma unroll
        for (int r = 0; r < 4; ++r)
          FFMA2(acc[r], pack2(((const float*)&av[r])[kk]), wv);
      }
    }
    __syncthreads();
  }
  // k-split merge: warps 8-15 (ks=16) publish; partner = w - 8
  ull* rd = (ull*)red;
  if (w >= 8) {
    ull* dst = rd + (((w - 8) * 32 + l) << 2);
#pragma unroll
    for (int r = 0; r < 4; ++r) dst[r] = acc[r];
  }
  __syncthreads();
  if (w < 8) {
    const ull* src = rd + ((w * 32 + l) << 2);
    union U { ull u; float2 f; };
#pragma unroll
    for (int r = 0; r < 4; ++r) {
      acc[r] = ADD2(acc[r], src[r]);
      int row = rg + r;
      U u; u.u = acc[r];
      float vals[2] = {u.f.x, u.f.y};
      float* og = outG ? outG[row] : 0;
#pragma unroll
      for (int j = 0; j < 2; ++j) {
        int col = cbase + j;
        float v = vals[j];
        if (bias) v += bias[col];
        if (epi == EPI_TANH) v = tanhf(v);
        else if (epi == EPI_CADJ) {
          float cs = tanhf(v);
          v = CAp[row * 128 + col] + cs * (dec[row] - 1.0f);
        }
        if (outS) outS[row * 128 + col] = v;
        else if (og) og[col] = v;
      }
    }
  }
  __syncthreads();
}

// ====== N=512 gates GEMM: 16 warps = 4rg(4 rows) x 4cg(128 cols) ===========
__device__ void gemm512(Pipe& P, const float* A1, const float* A2,
                        const float* Wx, const float* Wh, const float* bias, float* Z) {
  const int tid = threadIdx.x, w = tid >> 5, l = tid & 31;
  const int rg = ((w >> 2) & 3) << 2;  // 0,4,8,12
  const int cg = (w & 3) << 7;
  ull acc[4][2];
#pragma unroll
  for (int r = 0; r < 4; ++r) { acc[r][0] = 0; acc[r][1] = 0; }
  pissue(P, Wx, 32768, 0);
  for (int c = 0; c < 16; ++c) {
    if (c < 15) {
      const float* W = (c + 1 < 8) ? Wx : Wh;
      pissue(P, W + ((c + 1) & 7) * 16 * 512, 32768, 0);
    }
    const float* Wc = pwait(P);
    const float* A = (c < 8) ? A1 : A2;
    const int k0 = (c & 7) * 16;
#pragma unroll
    for (int kg = 0; kg < 4; ++kg) {
      float4 av[4];
#pragma unroll
      for (int r = 0; r < 4; ++r)
        av[r] = *(const float4*)&A[(rg + r) * 128 + k0 + kg * 4];
#pragma unroll
      for (int kk = 0; kk < 4; ++kk) {
        ulonglong2 wv = *(const ulonglong2*)&Wc[(kg * 4 + kk) * 512 + cg + (l << 2)];
#pragma unroll
        for (int r = 0; r < 4; ++r) {
          ull a = pack2(((const float*)&av[r])[kk]);
          FFMA2(acc[r][0], a, wv.x);
          FFMA2(acc[r][1], a, wv.y);
        }
      }
    }
    __syncthreads();
  }
  union U { ull u; float2 f; };
#pragma unroll
  for (int r = 0; r < 4; ++r) {
    U u0, u1; u0.u = acc[r][0]; u1.u = acc[r][1];
    float vals[4] = {u0.f.x, u0.f.y, u1.f.x, u1.f.y};
#pragma unroll
    for (int j = 0; j < 4; ++j) {
      int col = cg + (l << 2) + j;
      Z[(rg + r) * 512 + col] = vals[j] + bias[col];
    }
  }
  __syncthreads();
}

// ============================== main kernel =================================
__global__ void __launch_bounds__(NTHR) main_kernel(Params p) {
  extern __shared__ float sm[];
  float *X1 = sm, *X2 = sm + 2048, *E1 = sm + 4096, *E2 = sm + 6144;
  float *H1 = sm + 8192, *H2 = sm + 10240, *S1 = sm + 12288, *S2 = sm + 14336;
  float *CAb = sm + 16384, *Z = sm + 18432, *WS = sm + 26624;
  float *misc = sm + 43008;
  uint64_t* mbar = (uint64_t*)misc;
  int *slotH = (int*)(misc + 4), *slotT = slotH + 16, *valid = slotT + 16;
  float *decH = (float*)(valid + 16), *decT = decH + 16;
  float **og = (float**)(decT + 16);

  const int tid = threadIdx.x;
  const int gsize = gridDim.x * blockDim.x;
  const int gtid = blockIdx.x * blockDim.x + tid;
  const int S = p.S;

  Pipe P;
  P.wsp = WS;
  P.ws = (uint32_t)__cvta_generic_to_shared(WS);
  P.mb = (uint32_t)__cvta_generic_to_shared(mbar);
  P.ic = 0; P.wc = 0;
  if (tid == 0) { minit(P.mb); minit(P.mb + 8); }
  __syncthreads();

  for (int e = gtid; e < HSIZE * 32; e += gsize) {
    int slot = e >> 5, q = (e & 31) << 2;
    int node = g_slotNode[slot];
    if (node < 0) continue;
    size_t src = (size_t)node * 128 + q;
    size_t dst = (size_t)slot * 128 + q;
    *(float4*)&c_rep[dst] = *(const float4*)&p.node_rep[src];
    *(float4*)&c_ch[dst]  = *(const float4*)&p.cell_head[src];
    *(float4*)&c_hh[dst]  = *(const float4*)&p.hidden_head[src];
    *(float4*)&c_ct[dst]  = *(const float4*)&p.cell_tail[src];
    *(float4*)&c_ht[dst]  = *(const float4*)&p.hidden_tail[src];
    if (q == 0) c_rt[slot] = 0.0f;
  }
  grid_barrier();

  const int nW = g_numWaves;
  for (int w = 0; w < nW; ++w) {
    const int s0 = g_waveOff[w];
    const int M = g_waveOff[w + 1] - s0;

    if (M >= TILE_MIN) {
      const int mT = (M + 15) >> 4;
      for (int job = blockIdx.x; job < mT; job += gridDim.x) {
        int m0 = job * 16;
        if (tid < 16) {
          int m = m0 + tid;
          int v = (m < M);
          int step = g_stepList[s0 + (v ? m : (M - 1))];
          int ch = g_cidH[step], ct = g_cidT[step];
          slotH[tid] = ch; slotT[tid] = ct; valid[tid] = v;
          float tm = p.times[step];
          decH[tid] = expf(-(tm - c_rt[ch]));
          decT[tid] = expf(-(tm - c_rt[ct]));
          if (v) { c_rt[ch] = tm; c_rt[ct] = tm; }
        }
        __syncthreads();
        for (int e = tid; e < 512; e += NTHR) {
          int r = e >> 5, q = (e & 31) << 2;
          int ch = slotH[r], ct = slotT[r];
          float4 rh = *(const float4*)&c_rep[ch * 128 + q];
          float4 rt = *(const float4*)&c_rep[ct * 128 + q];
          *(float4*)&X1[r * 128 + q] = rh;
          *(float4*)&X2[r * 128 + q] = rt;
          *(float4*)&H1[r * 128 + q] = *(const float4*)&c_hh[ch * 128 + q];
          *(float4*)&H2[r * 128 + q] = *(const float4*)&c_ht[ct * 128 + q];
          *(float4*)&S1[r * 128 + q] = *(const float4*)&c_ht[ch * 128 + q];
          *(float4*)&S2[r * 128 + q] = *(const float4*)&c_hh[ct * 128 + q];
          if (valid[r]) {
            int step = g_stepList[s0 + m0 + r];
            *(float4*)&p.out[(size_t)step * 128 + q] = rh;
            *(float4*)&p.out[(size_t)(S + step) * 128 + q] = rt;
          }
        }
        __syncthreads();

        gemmEdge(P, p, X1, X2, E1, E2);

        for (int e = tid; e < 512; e += NTHR) {
          int r = e >> 5, q = (e & 31) << 2;
          *(float4*)&CAb[r * 128 + q] = *(const float4*)&c_ch[slotH[r] * 128 + q];
        }
        __syncthreads();
        gemm128(P, CAb, 0, p.Wdh, 0, p.bdh, EPI_CADJ, CAb, decH, X1, 0, Z);
        for (int e = tid; e < 512; e += NTHR) {
          int r = e >> 5, q = (e & 31) << 2;
          *(float4*)&CAb[r * 128 + q] = *(const float4*)&c_ct[slotT[r] * 128 + q];
        }
        __syncthreads();
        gemm128(P, CAb, 0, p.Wdt, 0, p.bdt, EPI_CADJ, CAb, decT, X2, 0, Z);

        for (int side = 0; side < 2; ++side) {
          if (side == 0) gemm512(P, E1, H1, p.Wxh, p.Whh, p.bh, Z);
          else           gemm512(P, E2, H2, p.Wxt, p.Wht, p.bt, Z);
          float* Xc = side ? X2 : X1;
          float* cel = side ? c_ct : c_ch;
          float* hid = side ? c_ht : c_hh;
          int* slot = side ? slotT : slotH;
          for (int e = tid; e < 2048; e += NTHR) {
            int r = e >> 7, c = e & 127;
            if (!valid[r]) continue;
            const float* z = &Z[r * 512];
            float ii = sigf(z[c]), ff = sigf(z[128 + c]);
            float oo = sigf(z[256 + c]), gg = tanhf(z[384 + c]);
            float cn = ff * Xc[r * 128 + c] + ii * gg;
            float hn = oo * tanhf(cn);
            Xc[r * 128 + c] = hn;
            cel[slot[r] * 128 + c] = cn;
            hid[slot[r] * 128 + c] = hn;
          }
          __syncthreads();
        }

        if (tid < 16)
          og[tid] = (valid[tid] && slotH[tid] != slotT[tid]) ? (c_rep + slotH[tid] * 128) : 0;
        __syncthreads();
        gemm128(P, X1, S1, p.Wc1, p.Wc2, 0, EPI_TANH, 0, 0, 0, og, Z);
        if (tid < 16) og[tid] = valid[tid] ? (c_rep + slotT[tid] * 128) : 0;
        __syncthreads();
        gemm128(P, S2, X2, p.Wc1, p.Wc2, 0, EPI_TANH, 0, 0, 0, og, Z);
      }
    } else {
      // ===== group-batched flag-gated tail: 8 steps per job, W read once ===
      // GEMV compute restricted to first 256 threads (act); copies use all.
      float *vA = sm, *vB = sm + 1024, *red = sm + 2048, *sdec = sm + 3072;
      const int nG = (M + 7) >> 3;
      const int nJ = 16 * nG;
      for (int j = blockIdx.x; j < nJ; j += NBLK) {
        int stage, g, sub;
        if (j < 4 * nG)       { stage = 0; g = j >> 2; sub = j & 3; }
        else if (j < 12 * nG) { stage = 1; int q = j - 4 * nG; g = q >> 3; sub = q & 7; }
        else if (j < 14 * nG) { stage = 2; int q = j - 12 * nG; g = q >> 1; sub = q & 1; }
        else                  { stage = 3; int q = j - 14 * nG; g = q >> 1; sub = q & 1; }
        const int pos = s0 + g * 8;
        const int cnt = min(8, M - g * 8);
        const int t = tid, col = t & 127, half = (t >> 7) & 1;
        const bool act = t < 256;

        if (stage == 0) {
          if (sub < 2) {
            for (int e = t; e < cnt * 128; e += NTHR) {
              int r = e >> 7, c = e & 127;
              int step = g_stepList[pos + r];
              float rh = c_rep[g_cidH[step] * 128 + c];
              float rt = c_rep[g_cidT[step] * 128 + c];
              vA[r * 128 + c] = rh; vB[r * 128 + c] = rt;
              if (sub == 0) {
                p.out[(size_t)step * 128 + c] = rh;
                p.out[(size_t)(S + step) * 128 + c] = rt;
              }
            }
            __syncthreads();
            float acc[8];
#pragma unroll
            for (int r = 0; r < 8; ++r) acc[r] = 0;
            if (act) {
              const float* W = half ? (sub ? p.Wet2 : p.Weh2) : (sub ? p.Wet1 : p.Weh1);
              const float* A = half ? vB : vA;
              for (int k0 = 0; k0 < 128; k0 += 4) {
                float4 av[8];
#pragma unroll
                for (int r = 0; r < 8; ++r) av[r] = *(const float4*)&A[r * 128 + k0];
#pragma unroll
                for (int kk = 0; kk < 4; ++kk) {
                  float wv = W[(k0 + kk) * 128 + col];
#pragma unroll
                  for (int r = 0; r < 8; ++r) acc[r] += ((const float*)&av[r])[kk] * wv;
                }
              }
              if (half)
#pragma unroll
                for (int r = 0; r < 8; ++r) red[r * 128 + col] = acc[r];
            }
            __syncthreads();
            if (act && !half) {
              const float* bb = sub ? p.bet : p.beh;
              float* E = sub ? bE2 : bE1;
              for (int r = 0; r < cnt; ++r)
                E[(g * 8 + r) * 128 + col] = tanhf(acc[r] + red[r * 128 + col] + bb[col]);
            }
          } else {
            int isH = (sub == 2);
            for (int e = t; e < cnt * 128; e += NTHR) {
              int r = e >> 7, c = e & 127;
              int step = g_stepList[pos + r];
              int slot = isH ? g_cidH[step] : g_cidT[step];
              vA[r * 128 + c] = (isH ? c_ch : c_ct)[slot * 128 + c];
              if (isH) bTh[(g * 8 + r) * 128 + c] = c_ht[g_cidH[step] * 128 + c];
              else     bHt[(g * 8 + r) * 128 + c] = c_hh[g_cidT[step] * 128 + c];
              if (c == 0) sdec[r] = expf(-(p.times[step] - c_rt[slot]));
            }
            __syncthreads();
            float acc[8];
#pragma unroll
            for (int r = 0; r < 8; ++r) acc[r] = 0;
            if (act) {
              const float* W = isH ? p.Wdh : p.Wdt;
              for (int k0 = half * 64; k0 < half * 64 + 64; k0 += 4) {
                float4 av[8];
#pragma unroll
                for (int r = 0; r < 8; ++r) av[r] = *(const float4*)&vA[r * 128 + k0];
#pragma unroll
                for (int kk = 0; kk < 4; ++kk) {
                  float wv = W[(k0 + kk) * 128 + col];
#pragma unroll
                  for (int r = 0; r < 8; ++r) acc[r] += ((const float*)&av[r])[kk] * wv;
                }
              }
              if (half)
#pragma unroll
                for (int r = 0; r < 8; ++r) red[r * 128 + col] = acc[r];
            }
            __syncthreads();
            if (act && !half) {
              const float* bd = isH ? p.bdh : p.bdt;
              float* CJ = isH ? bCJH : bCJT;
              for (int r = 0; r < cnt; ++r) {
                float cs = tanhf(acc[r] + red[r * 128 + col] + bd[col]);
                CJ[(g * 8 + r) * 128 + col] = vA[r * 128 + col] + cs * (sdec[r] - 1.0f);
              }
            }
          }
          __threadfence();
          __syncthreads();
          if (t == 0) atomicAdd(&g_flagA[pos], 1);
        } else if (stage == 1) {
          int side = sub & 1, gate = sub >> 1;
          if (t == 0) {
            while (atomicAdd(&g_flagA[pos], 0) < 4) __nanosleep(64);
            __threadfence();
          }
          __syncthreads();
          for (int e = t; e < cnt * 128; e += NTHR) {
            int r = e >> 7, c = e & 127;
            int step = g_stepList[pos + r];
            vA[r * 128 + c] = (side ? bE2 : bE1)[(g * 8 + r) * 128 + c];
            vB[r * 128 + c] = side ? c_ht[g_cidT[step] * 128 + c]
                                   : c_hh[g_cidH[step] * 128 + c];
          }
          __syncthreads();
          float acc[8];
#pragma unroll
          for (int r = 0; r < 8; ++r) acc[r] = 0;
          int gcol = gate * 128 + col;
          if (act) {
            const float* W = half ? (side ? p.Wht : p.Whh) : (side ? p.Wxt : p.Wxh);
            const float* A = half ? vB : vA;
            for (int k0 = 0; k0 < 128; k0 += 4) {
              float4 av[8];
#pragma unroll
              for (int r = 0; r < 8; ++r) av[r] = *(const float4*)&A[r * 128 + k0];
#pragma unroll
              for (int kk = 0; kk < 4; ++kk) {
                float wv = W[(k0 + kk) * 512 + gcol];
#pragma unroll
                for (int r = 0; r < 8; ++r) acc[r] += ((const float*)&av[r])[kk] * wv;
              }
            }
            if (half)
#pragma unroll
              for (int r = 0; r < 8; ++r) red[r * 128 + col] = acc[r];
          }
          __syncthreads();
          if (act && !half) {
            const float* bb = side ? p.bt : p.bh;
            for (int r = 0; r < cnt; ++r)
              bZ[(g * 8 + r) * 1024 + side * 512 + gcol] =
                  acc[r] + red[r * 128 + col] + bb[gcol];
          }
          __threadfence();
          __syncthreads();
          if (t == 0) atomicAdd(&g_flagB[2 * pos + side], 1);
        } else if (stage == 2) {
          int side = sub;
          if (t == 0) {
            while (atomicAdd(&g_flagB[2 * pos + side], 0) < 4) __nanosleep(64);
            __threadfence();
          }
          __syncthreads();
          for (int e = t; e < cnt * 128; e += NTHR) {
            int r = e >> 7, c = e & 127;
            int step = g_stepList[pos + r];
            int slot = side ? g_cidT[step] : g_cidH[step];
            const float* z = &bZ[(g * 8 + r) * 1024 + side * 512];
            float ii = sigf(z[c]), ff = sigf(z[128 + c]);
            float oo = sigf(z[256 + c]), gg = tanhf(z[384 + c]);
            float cj = (side ? bCJT : bCJH)[(g * 8 + r) * 128 + c];
            float cn = ff * cj + ii * gg;
            float hn = oo * tanhf(cn);
            (side ? bHnT : bHnH)[(g * 8 + r) * 128 + c] = hn;
            (side ? c_ct : c_ch)[slot * 128 + c] = cn;
            (side ? c_ht : c_hh)[slot * 128 + c] = hn;
            if (c == 0) c_rt[slot] = p.times[step];
          }
          __threadfence();
          __syncthreads();
          if (t == 0) atomicAdd(&g_flagC[2 * pos + side], 1);
        } else {
          int side = sub;
          if (t == 0) {
            while (atomicAdd(&g_flagC[2 * pos + side], 0) < 1) __nanosleep(64);
            __threadfence();
          }
          __syncthreads();
          for (int e = t; e < cnt * 128; e += NTHR) {
            int r = e >> 7, c = e & 127;
            vA[r * 128 + c] = (side ? bHt : bHnH)[(g * 8 + r) * 128 + c];
            vB[r * 128 + c] = (side ? bHnT : bTh)[(g * 8 + r) * 128 + c];
          }
          __syncthreads();
          float acc[8];
#pragma unroll
          for (int r = 0; r < 8; ++r) acc[r] = 0;
          if (act) {
            const float* W = half ? p.Wc2 : p.Wc1;
            const float* A = half ? vB : vA;
            for (int k0 = 0; k0 < 128; k0 += 4) {
              float4 av[8];
#pragma unroll
              for (int r = 0; r < 8; ++r) av[r] = *(const float4*)&A[r * 128 + k0];
#pragma unroll
              for (int kk = 0; kk < 4; ++kk) {
                float wv = W[(k0 + kk) * 128 + col];
#pragma unroll
                for (int r = 0; r < 8; ++r) acc[r] += ((const float*)&av[r])[kk] * wv;
              }
            }
            if (half)
#pragma unroll
              for (int r = 0; r < 8; ++r) red[r * 128 + col] = acc[r];
          }
          __syncthreads();
          if (act && !half) {
            for (int r = 0; r < cnt; ++r) {
              int step = g_stepList[pos + r];
              int ch = g_cidH[step], ct = g_cidT[step];
              if (side || ch != ct)
                c_rep[(side ? ct : ch) * 128 + col] =
                    tanhf(acc[r] + red[r * 128 + col]);
            }
          }
          __syncthreads();
        }
      }
    }
    grid_barrier();
  }
}

// ============================================================================
extern "C" void kernel_launch(void* const* d_in, const int* in_sizes, int n_in,
                              void* d_out, int out_size) {
  Params p;
  p.heads = (const int*)d_in[0];  p.tails = (const int*)d_in[1];
  p.times = (const float*)d_in[2];
  p.node_rep = (const float*)d_in[3];  p.cell_head = (const float*)d_in[4];
  p.hidden_head = (const float*)d_in[5]; p.cell_tail = (const float*)d_in[6];
  p.hidden_tail = (const float*)d_in[7];
  p.Weh1 = (const float*)d_in[8];  p.Weh2 = (const float*)d_in[9];  p.beh = (const float*)d_in[10];
  p.Wet1 = (const float*)d_in[11]; p.Wet2 = (const float*)d_in[12]; p.bet = (const float*)d_in[13];
  p.Wxh = (const float*)d_in[14];  p.Whh = (const float*)d_in[15];  p.bh = (const float*)d_in[16];
  p.Wdh = (const float*)d_in[17];  p.bdh = (const float*)d_in[18];
  p.Wxt = (const float*)d_in[19];  p.Wht = (const float*)d_in[20];  p.bt = (const float*)d_in[21];
  p.Wdt = (const float*)d_in[22];  p.bdt = (const float*)d_in[23];
  p.Wc1 = (const float*)d_in[24];  p.Wc2 = (const float*)d_in[25];
  p.out = (float*)d_out;
  p.S = in_sizes[0];

  cudaFuncSetAttribute(main_kernel, cudaFuncAttributeMaxDynamicSharedMemorySize, SMEMB);
  scheduler_kernel<<<1, 1024>>>(p.heads, p.tails, p.S);
  main_kernel<<<NBLK, NTHR, SMEMB>>>(p);
}